// round 15
// baseline (speedup 1.0000x reference)
#include <cuda_runtime.h>
#include <math.h>
#include <stdint.h>

#define NN     8192
#define NB     8192
#define RANGEF 74000.0f
#define INV_W  ((float)NB / RANGEF)

// Scratch (__device__ globals; zero-initialized at load; g_A reset in K2,
// g_hist zeroed in K3 -> every graph replay sees identical initial state).
__device__ float g_A[NN];       // edge segment sums
__device__ float g_S[NN];       // S per node (original order)
__device__ float g_V[NN];       // bucket-grouped copy of S
__device__ int   g_hist[NB];    // histogram
__device__ int   g_P[NB + 1];   // exclusive prefix
__device__ float g_C;           // dot(x, p)

// Monotone bucket map. MUST be identical at insert (K2/K3) and query (K4).
__device__ __forceinline__ int bucket_of(float v, float C) {
    float u = (v - C) * INV_W;
    int b = (int)u;
    if (b < 0) b = 0;
    if (b > NB - 1) b = NB - 1;
    return b;
}

// HW tanh (MUFU.TANH). Abs err ~2^-10.6 — band terms only, negligible.
__device__ __forceinline__ float tanh_fast(float a) {
    float r;
    asm("tanh.approx.f32 %0, %1;" : "=f"(r) : "f"(a));
    return r;
}

// ---------------------------------------------------------------------------
// K1: edges on blocks 0..255 (4 edges/thread via int4) + dot on block 256.
__global__ void __launch_bounds__(256, 2)
k1_edges_dot(const int* __restrict__ ei, const float* __restrict__ p,
             const float* __restrict__ x, int E, int n) {
    const int t = threadIdx.x;
    if (blockIdx.x == 256) {
        // Deterministic double dot: fixed order every run.
        __shared__ double dred[8];
        double acc = 0.0;
        for (int i = t; i < n; i += 256)
            acc += (double)__ldg(&x[i]) * (double)__ldg(&p[i]);
#pragma unroll
        for (int o = 16; o > 0; o >>= 1)
            acc += __shfl_down_sync(0xffffffffu, acc, o);
        if ((t & 31) == 0) dred[t >> 5] = acc;
        __syncthreads();
        if (t == 0) {
            double s = 0.0;
#pragma unroll
            for (int w = 0; w < 8; w++) s += dred[w];
            g_C = (float)s;
        }
        return;
    }

    const int tid  = blockIdx.x * 256 + t;
    const int nthr = 256 * 256;
    if ((E & 3) == 0 && (((unsigned long long)ei) & 15ull) == 0) {
        const int  E4 = E >> 2;
        const int4* s4 = (const int4*)ei;
        const int4* d4 = (const int4*)(ei + E);
        for (int j = tid; j < E4; j += nthr) {        // exactly 1 iter here
            int4 s = __ldg(&s4[j]);
            int4 d = __ldg(&d4[j]);
            float p0 = __ldg(&p[s.x]);
            float p1 = __ldg(&p[s.y]);
            float p2 = __ldg(&p[s.z]);
            float p3 = __ldg(&p[s.w]);
            atomicAdd(&g_A[d.x], p0);                 // REDG fire-and-forget
            atomicAdd(&g_A[d.y], p1);
            atomicAdd(&g_A[d.z], p2);
            atomicAdd(&g_A[d.w], p3);
        }
    } else {
        for (int e = tid; e < E; e += nthr) {
            int s = __ldg(&ei[e]);
            int d = __ldg(&ei[E + e]);
            atomicAdd(&g_A[d], __ldg(&p[s]));
        }
    }
}

// ---------------------------------------------------------------------------
// K2: distributed S + histogram. 16 blocks x 512 threads, 1 node/thread.
__global__ void __launch_bounds__(512, 2)
k2_S_hist(const float* __restrict__ p, int n, float logn) {
    const int i = blockIdx.x * 512 + threadIdx.x;
    if (i >= n) return;
    const float C = *(volatile float*)&g_C;
    float A  = __ldcg(&g_A[i]);              // L2 (REDG-written)
    g_A[i]   = 0.0f;                         // restore invariant for replay
    float pi = __ldg(&p[i]);
    float s  = pi * logn + __logf(pi + A) + C;   // __logf: sub-ulp of S scale
    g_S[i]   = s;
    atomicAdd(&g_hist[bucket_of(s, C)], 1);  // REDG, ~1 op/bin
}

// ---------------------------------------------------------------------------
// K3: single block: scan 8192 bins, publish g_P, counting-sort g_S -> g_V.
__global__ void __launch_bounds__(1024, 1)
k3_scan_scatter(int n) {
    __shared__ int cnt[NB];
    __shared__ int wsum[32];
    const int t = threadIdx.x;
    const int lane = t & 31, wid = t >> 5;

    // Load histogram (coalesced), zero it in global for next replay.
    int c8[8];
    const int base8 = t * 8;
#pragma unroll
    for (int k = 0; k < 8; k++) {
        c8[k] = __ldcg(&g_hist[base8 + k]);
        g_hist[base8 + k] = 0;
    }
    int ex[8], tot = 0;
#pragma unroll
    for (int k = 0; k < 8; k++) { ex[k] = tot; tot += c8[k]; }

    int v = tot;
#pragma unroll
    for (int o = 1; o < 32; o <<= 1) {
        int u = __shfl_up_sync(0xffffffffu, v, o);
        if (lane >= o) v += u;
    }
    if (lane == 31) wsum[wid] = v;
    __syncthreads();
    if (wid == 0) {
        int w = wsum[lane];
#pragma unroll
        for (int o = 1; o < 32; o <<= 1) {
            int u = __shfl_up_sync(0xffffffffu, w, o);
            if (lane >= o) w += u;
        }
        wsum[lane] = w;
    }
    __syncthreads();
    int excl = v - tot + (wid ? wsum[wid - 1] : 0);

#pragma unroll
    for (int k = 0; k < 8; k++) {
        int pref = excl + ex[k];
        cnt[base8 + k] = pref;               // live counters for scatter
        g_P[base8 + k] = pref;               // published prefix
    }
    if (t == 1023) g_P[NB] = excl + tot;     // = n
    __syncthreads();

    // Counting-sort scatter (read g_S coalesced; random STG to g_V).
    const float C = *(volatile float*)&g_C;
#pragma unroll
    for (int k = 0; k < NN / 1024; k++) {
        int i = t + 1024 * k;
        if (i < n) {
            float s = __ldcg(&g_S[i]);
            int pos = atomicAdd(&cnt[bucket_of(s, C)], 1);
            g_V[pos] = s;
        }
    }
}

// ---------------------------------------------------------------------------
// K4: output. 64 blocks x 128 threads, 1 node/thread.
// out[i] = sum_j tanh(1000*(S_i - S_j) - 5). Outside band
// [Si-0.015, Si+0.005]: exactly saturated (+1/-1) -> prefix counts.
// Band buckets: exact per-element evaluation (incl. diagonal j=i).
__global__ void __launch_bounds__(128, 8)
k4_out(float* __restrict__ out, int n) {
    const int i = blockIdx.x * 128 + threadIdx.x;
    if (i >= n) return;

    const float K   = 1000.0f;
    const float EPS = 5.0f;
    const float CUT = 10.0f;

    const float C  = *(volatile float*)&g_C;
    const float Si = __ldcg(&g_S[i]);

    int loB = bucket_of(Si - 0.015f, C);
    int hiB = bucket_of(Si + 0.005f, C);

    int pLo = __ldcg(&g_P[loB]);
    int pHi = __ldcg(&g_P[hiB + 1]);
    float acc = (float)pLo - (float)(n - pHi);

    for (int idx = pLo; idx < pHi; ++idx) {
        float w   = __ldcg(&g_V[idx]);
        float arg = K * (Si - w) - EPS;
        if (arg > CUT)        acc += 1.0f;
        else if (arg < -CUT)  acc -= 1.0f;
        else                  acc += tanh_fast(arg);
    }
    out[i] = acc;
}

// ---------------------------------------------------------------------------
extern "C" void kernel_launch(void* const* d_in, const int* in_sizes, int n_in,
                              void* d_out, int out_size) {
    const int*   ei = (const int*)d_in[0];     // (2, E) row-major
    const float* p  = (const float*)d_in[1];   // (N,)
    const float* x  = (const float*)d_in[2];   // (N, 1)

    int E = in_sizes[0] / 2;
    int n = in_sizes[1];
    float logn = logf((float)n);

    k1_edges_dot<<<257, 256>>>(ei, p, x, E, n);
    k2_S_hist<<<16, 512>>>(p, n, logn);
    k3_scan_scatter<<<1, 1024>>>(n);
    k4_out<<<(n + 127) / 128, 128>>>((float*)d_out, n);
}